// round 16
// baseline (speedup 1.0000x reference)
#include <cuda_runtime.h>
#include <cuda_fp16.h>
#include <math.h>
#include <stdint.h>

#define T_TOK 8192
#define H_DIM 1024
#define E_NUM 8
#define I_DIM 2048

// ---------------- device-global scratch -------------------------------------
__device__ int   d_cnt[E_NUM];
__device__ float d_psum[E_NUM];
__device__ int   d_tok[E_NUM * T_TOK];
__device__ float d_cw [E_NUM * T_TOK];

__device__ __half g_xh[(size_t)T_TOK * H_DIM];
__device__ __half g_w1h[(size_t)E_NUM * I_DIM * H_DIM];
__device__ __half g_w3h[(size_t)E_NUM * I_DIM * H_DIM];
__device__ __half g_w2h[(size_t)E_NUM * H_DIM * I_DIM];
__device__ __half g_hidh[(size_t)E_NUM * T_TOK * I_DIM];   // slot-indexed

// ---------------- PTX helpers (baseline ISA only) ----------------------------
__device__ __forceinline__ uint32_t smem_u32(const void* p) {
    uint32_t r;
    asm("{ .reg .u64 t; cvta.to.shared.u64 t, %1; cvt.u32.u64 %0, t; }"
        : "=r"(r) : "l"(p));
    return r;
}
__device__ __forceinline__ void cp16(uint32_t saddr, const void* gaddr) {
    asm volatile("cp.async.cg.shared.global [%0], [%1], 16;"
                 :: "r"(saddr), "l"(gaddr));
}
__device__ __forceinline__ void cp_commit() {
    asm volatile("cp.async.commit_group;");
}
template <int N> __device__ __forceinline__ void cp_wait() {
    asm volatile("cp.async.wait_group %0;" :: "n"(N));
}
__device__ __forceinline__ void ldsm4(uint32_t* r, uint32_t addr) {
    asm volatile("ldmatrix.sync.aligned.m8n8.x4.shared.b16 {%0,%1,%2,%3}, [%4];"
                 : "=r"(r[0]), "=r"(r[1]), "=r"(r[2]), "=r"(r[3]) : "r"(addr));
}
__device__ __forceinline__ void mma16816(float* d, const uint32_t* a,
                                         const uint32_t* b) {
    asm volatile(
        "mma.sync.aligned.m16n8k16.row.col.f32.f16.f16.f32 "
        "{%0,%1,%2,%3}, {%4,%5,%6,%7}, {%8,%9}, {%0,%1,%2,%3};"
        : "+f"(d[0]), "+f"(d[1]), "+f"(d[2]), "+f"(d[3])
        : "r"(a[0]), "r"(a[1]), "r"(a[2]), "r"(a[3]), "r"(b[0]), "r"(b[1]));
}
// swizzled address inside a [rows][64B] tile: conflict-free for ldmatrix+STS
__device__ __forceinline__ uint32_t tile_addr(uint32_t base, int row, int chunk) {
    return base + row * 64 + ((chunk ^ ((row >> 1) & 3)) << 4);
}
__device__ __forceinline__ uint32_t pack_h2(__half a, __half b) {
    __half2 t = __halves2half2(a, b);
    return *reinterpret_cast<uint32_t*>(&t);
}

// ---------------- small kernels ----------------------------------------------
__global__ void zero_kernel() {
    int i = threadIdx.x;
    if (i < E_NUM) { d_cnt[i] = 0; d_psum[i] = 0.f; }
}

// gate: logits/softmax/top2 + writes g_xh (fused x conversion)
__global__ void gate_kernel(const float* __restrict__ x,
                            const float* __restrict__ gw) {
    int tok  = (blockIdx.x * blockDim.x + threadIdx.x) >> 5;
    int lane = threadIdx.x & 31;
    int wib  = threadIdx.x >> 5;
    __shared__ float sprob[8][E_NUM];

    float acc[E_NUM];
#pragma unroll
    for (int e = 0; e < E_NUM; e++) acc[e] = 0.f;
    const float* xr = x + (size_t)tok * H_DIM;
    __half* xh = g_xh + (size_t)tok * H_DIM;
    for (int h = lane; h < H_DIM; h += 32) {
        float xv = xr[h];
        xh[h] = __float2half(xv);
#pragma unroll
        for (int e = 0; e < E_NUM; e++)
            acc[e] = fmaf(xv, gw[e * H_DIM + h], acc[e]);
    }
#pragma unroll
    for (int e = 0; e < E_NUM; e++)
#pragma unroll
        for (int o = 16; o > 0; o >>= 1)
            acc[e] += __shfl_xor_sync(0xffffffffu, acc[e], o);

    if (lane == 0) {
        float mx = acc[0];
#pragma unroll
        for (int e = 1; e < E_NUM; e++) mx = fmaxf(mx, acc[e]);
        float p[E_NUM], s = 0.f;
#pragma unroll
        for (int e = 0; e < E_NUM; e++) { p[e] = expf(acc[e] - mx); s += p[e]; }
        float inv = 1.f / s;
#pragma unroll
        for (int e = 0; e < E_NUM; e++) { p[e] *= inv; sprob[wib][e] = p[e]; }

        int i0 = 0; float v0 = p[0];
#pragma unroll
        for (int e = 1; e < E_NUM; e++) if (p[e] > v0) { v0 = p[e]; i0 = e; }
        int i1 = -1; float v1 = -1.f;
#pragma unroll
        for (int e = 0; e < E_NUM; e++)
            if (e != i0 && p[e] > v1) { v1 = p[e]; i1 = e; }

        float wn  = 1.f / (v0 + v1 + 1e-6f);
        int p0 = atomicAdd(&d_cnt[i0], 1);
        d_tok[i0 * T_TOK + p0] = tok;  d_cw[i0 * T_TOK + p0] = v0 * wn;
        int p1 = atomicAdd(&d_cnt[i1], 1);
        d_tok[i1 * T_TOK + p1] = tok;  d_cw[i1 * T_TOK + p1] = v1 * wn;
    }
    __syncthreads();
    if (threadIdx.x < E_NUM) {
        float s = 0.f;
#pragma unroll
        for (int w = 0; w < 8; w++) s += sprob[w][threadIdx.x];
        atomicAdd(&d_psum[threadIdx.x], s);
    }
}

// fused weight conversion (w1, w2, w3): 8 floats per thread (MLP 2)
#define NW (E_NUM * I_DIM * H_DIM)
__global__ void cvt_w_kernel(const float* __restrict__ w1,
                             const float* __restrict__ w2,
                             const float* __restrict__ w3) {
    size_t i = ((size_t)blockIdx.x * blockDim.x + threadIdx.x) * 8;
    const float* src;
    __half* dst;
    size_t off;
    if (i < NW)                  { src = w1; dst = g_w1h; off = i; }
    else if (i < 2 * (size_t)NW) { src = w2; dst = g_w2h; off = i - NW; }
    else if (i < 3 * (size_t)NW) { src = w3; dst = g_w3h; off = i - 2 * (size_t)NW; }
    else return;
    float4 v0 = *(const float4*)(src + off);
    float4 v1 = *(const float4*)(src + off + 4);
    uint4 H;
    H.x = pack_h2(__float2half(v0.x), __float2half(v0.y));
    H.y = pack_h2(__float2half(v0.z), __float2half(v0.w));
    H.z = pack_h2(__float2half(v1.x), __float2half(v1.y));
    H.w = pack_h2(__float2half(v1.z), __float2half(v1.w));
    *(uint4*)(dst + off) = H;
}

// ---------------- GEMM tile constants ----------------------------------------
// stage (16 KB): A[128][64B], B[128][64B]. 6 stages = 96 KB. 256 thr, occ 2.
#define TS_A 0
#define TS_B 8192
#define STAGE 16384
#define NSTAGE 6
#define EPI_STRIDE 68
#define F1_SMEM (NSTAGE * STAGE)   // 98304 >= epilogue 69632
#define F2_SMEM (NSTAGE * STAGE)

// ---------------- FFN1: h = silu(x w1^T) * (x w3^T) --------------------------
// block tile: M=128 routed rows, N=64 intermediate cols for both w1 & w3.
// B smem rows 0-63 = w1h[n0..], 64-127 = w3h[n0..]. 8 warps (wM 0-1)x(wN 0-3).
__global__ void __launch_bounds__(256, 2)
ffn1_kernel() {
    extern __shared__ char smem[];
    __shared__ int stok[128];
    const int e   = blockIdx.z;
    const int cnt = d_cnt[e];
    const int m0  = blockIdx.y * 128;
    if (m0 >= cnt) return;
    const int n0  = blockIdx.x * 64;

    const uint32_t sb = smem_u32(smem);
    const int tid = threadIdx.x, lane = tid & 31, wid = tid >> 5;
    const int wM = wid >> 2, wN = wid & 3;

    if (tid < 128) stok[tid] = (m0 + tid < cnt) ? d_tok[e * T_TOK + m0 + tid] : 0;
    __syncthreads();

    // ---- precomputed loader state: pure pointer-increment per stage ----
    const __half* gsrc[4];
    uint32_t sdst[4];
#pragma unroll
    for (int t = 0; t < 4; t++) {
        int i = tid + t * 256;
        int region = i >> 9;          // 0 A, 1 B
        int idx = i & 511;
        int row = idx >> 2, c = idx & 3;
        sdst[t] = tile_addr(sb + region * 8192, row, c);
        if (region == 0) {
            gsrc[t] = g_xh + (size_t)stok[row] * H_DIM + c * 8;
        } else {
            const __half* s_ = (row < 64) ? g_w1h : g_w3h;
            int r = row & 63;
            gsrc[t] = s_ + ((size_t)e * I_DIM + n0 + r) * H_DIM + c * 8;
        }
    }
    auto load_stage = [&](int s) {
#pragma unroll
        for (int t = 0; t < 4; t++) {
            cp16(sdst[t] + s * STAGE, gsrc[t]);
            gsrc[t] += 32;
        }
    };

    // ---- ldmatrix addresses for ks=0; ks=1 = addr ^ 32 (swizzle identity) ----
    uint32_t aaddr[4], baddr[2];
    {
        const int cb = (lane >> 4);
#pragma unroll
        for (int mt = 0; mt < 4; mt++)
            aaddr[mt] = tile_addr(sb + TS_A, wM * 64 + mt * 16 + (lane & 15), cb);
#pragma unroll
        for (int p = 0; p < 2; p++)
            baddr[p] = tile_addr(sb + TS_B, wN * 32 + p * 16 + (lane & 15), cb);
    }

    float acc[4][4][4];
#pragma unroll
    for (int mt = 0; mt < 4; mt++)
#pragma unroll
        for (int nt = 0; nt < 4; nt++)
#pragma unroll
            for (int q = 0; q < 4; q++) acc[mt][nt][q] = 0.f;

    const int NK = H_DIM / 32;
    load_stage(0); cp_commit();
    load_stage(1); cp_commit();
    load_stage(2); cp_commit();
    load_stage(3); cp_commit();
    load_stage(4); cp_commit();

    int s = 0, sl = 5;
    for (int k = 0; k < NK; k++) {
        cp_wait<4>();
        __syncthreads();
        const uint32_t soff = (uint32_t)s * STAGE;

        uint32_t a[4][4], b0[2][4], b1[2][4];
#pragma unroll
        for (int mt = 0; mt < 4; mt++) ldsm4(a[mt], aaddr[mt] + soff);
#pragma unroll
        for (int p = 0; p < 2; p++)    ldsm4(b0[p], baddr[p] + soff);
#pragma unroll
        for (int p = 0; p < 2; p++)    ldsm4(b1[p], (baddr[p] + soff) ^ 32);
        // ks = 0
#pragma unroll
        for (int mt = 0; mt < 4; mt++)
#pragma unroll
            for (int nt = 0; nt < 4; nt++) {
                int p = nt >> 1, o = nt & 1;
                uint32_t b2[2] = {b0[p][o], b0[p][o + 2]};
                mma16816(acc[mt][nt], a[mt], b2);
            }
        // ks = 1 (reuse A register set)
#pragma unroll
        for (int mt = 0; mt < 4; mt++) ldsm4(a[mt], (aaddr[mt] + soff) ^ 32);
#pragma unroll
        for (int mt = 0; mt < 4; mt++)
#pragma unroll
            for (int nt = 0; nt < 4; nt++) {
                int p = nt >> 1, o = nt & 1;
                uint32_t b2[2] = {b1[p][o], b1[p][o + 2]};
                mma16816(acc[mt][nt], a[mt], b2);
            }

        if (k + 5 < NK) load_stage(sl);
        cp_commit();
        s  = (s  == NSTAGE - 1) ? 0 : s + 1;
        sl = (sl == NSTAGE - 1) ? 0 : sl + 1;
    }
    __syncthreads();   // before epilogue aliases stage smem

    // epilogue: stash g/u in smem, combine, convert to fp16
    float* Sg = (float*)smem;
    float* Su = Sg + 128 * EPI_STRIDE;
    float* Sacc = (wN < 2) ? Sg : Su;
    const int ncb = (wN & 1) * 32;
#pragma unroll
    for (int mt = 0; mt < 4; mt++) {
        int row = wM * 64 + mt * 16 + (lane >> 2);
#pragma unroll
        for (int nt = 0; nt < 4; nt++) {
            int col = ncb + nt * 8 + (lane & 3) * 2;
            Sacc[row * EPI_STRIDE + col]     = acc[mt][nt][0];
            Sacc[row * EPI_STRIDE + col + 1] = acc[mt][nt][1];
            Sacc[(row + 8) * EPI_STRIDE + col]     = acc[mt][nt][2];
            Sacc[(row + 8) * EPI_STRIDE + col + 1] = acc[mt][nt][3];
        }
    }
    __syncthreads();

    const size_t slotbase = (size_t)e * T_TOK + m0;
    for (int idx = tid; idx < 128 * 32; idx += 256) {
        int m = idx >> 5;
        if (m0 + m >= cnt) continue;
        int c = (idx & 31) * 2;
        float g0 = Sg[m * EPI_STRIDE + c], g1 = Sg[m * EPI_STRIDE + c + 1];
        float u0 = Su[m * EPI_STRIDE + c], u1 = Su[m * EPI_STRIDE + c + 1];
        float h0 = (g0 / (1.f + __expf(-g0))) * u0;
        float h1 = (g1 / (1.f + __expf(-g1))) * u1;
        *(uint32_t*)(g_hidh + (slotbase + m) * I_DIM + n0 + c) =
            pack_h2(__float2half(h0), __float2half(h1));
    }
}

// ---------------- FFN2: out[tok] += cw * (hidden w2^T) -----------------------
// block tile M=128, N=128 (H cols). 8 warps (wM 0-1)x(wN 0-3), 64x32 each.
// Writes straight to out with atomicAdd (out pre-zeroed).
__global__ void __launch_bounds__(256, 2)
ffn2_kernel(float* __restrict__ out) {
    extern __shared__ char smem[];
    __shared__ float scw[128];
    __shared__ int   stok2[128];
    const int e   = blockIdx.z;
    const int cnt = d_cnt[e];
    const int m0  = blockIdx.y * 128;
    if (m0 >= cnt) return;
    const int n0  = blockIdx.x * 128;
    const size_t slotbase = (size_t)e * T_TOK + m0;

    const uint32_t sb = smem_u32(smem);
    const int tid = threadIdx.x, lane = tid & 31, wid = tid >> 5;
    const int wM = wid >> 2, wN = wid & 3;

    if (tid < 128) {
        bool v = (m0 + tid < cnt);
        scw[tid]   = v ? d_cw[e * T_TOK + m0 + tid] : 0.f;
        stok2[tid] = v ? d_tok[e * T_TOK + m0 + tid] : 0;
    }
    __syncthreads();

    const __half* gsrc[4];
    uint32_t sdst[4];
#pragma unroll
    for (int t = 0; t < 4; t++) {
        int i = tid + t * 256;
        int region = i >> 9;
        int idx = i & 511;
        int row = idx >> 2, c = idx & 3;
        sdst[t] = tile_addr(sb + region * 8192, row, c);
        if (region == 0)
            gsrc[t] = g_hidh + (slotbase + row) * I_DIM + c * 8;
        else
            gsrc[t] = g_w2h + ((size_t)e * H_DIM + n0 + row) * I_DIM + c * 8;
    }
    auto load_stage = [&](int s) {
#pragma unroll
        for (int t = 0; t < 4; t++) {
            cp16(sdst[t] + s * STAGE, gsrc[t]);
            gsrc[t] += 32;
        }
    };

    uint32_t aaddr[4], baddr[2];
    {
        const int cb = (lane >> 4);
#pragma unroll
        for (int mt = 0; mt < 4; mt++)
            aaddr[mt] = tile_addr(sb + TS_A, wM * 64 + mt * 16 + (lane & 15), cb);
#pragma unroll
        for (int p = 0; p < 2; p++)
            baddr[p] = tile_addr(sb + TS_B, wN * 32 + p * 16 + (lane & 15), cb);
    }

    float acc[4][4][4];
#pragma unroll
    for (int mt = 0; mt < 4; mt++)
#pragma unroll
        for (int nt = 0; nt < 4; nt++)
#pragma unroll
            for (int q = 0; q < 4; q++) acc[mt][nt][q] = 0.f;

    const int NK = I_DIM / 32;
    load_stage(0); cp_commit();
    load_stage(1); cp_commit();
    load_stage(2); cp_commit();
    load_stage(3); cp_commit();
    load_stage(4); cp_commit();

    int s = 0, sl = 5;
    for (int k = 0; k < NK; k++) {
        cp_wait<4>();
        __syncthreads();
        const uint32_t soff = (uint32_t)s * STAGE;

        uint32_t a[4][4], b0[2][4], b1[2][4];
#pragma unroll
        for (int mt = 0; mt < 4; mt++) ldsm4(a[mt], aaddr[mt] + soff);
#pragma unroll
        for (int p = 0; p < 2; p++)    ldsm4(b0[p], baddr[p] + soff);
#pragma unroll
        for (int p = 0; p < 2; p++)    ldsm4(b1[p], (baddr[p] + soff) ^ 32);
#pragma unroll
        for (int mt = 0; mt < 4; mt++)
#pragma unroll
            for (int nt = 0; nt < 4; nt++) {
                int p = nt >> 1, o = nt & 1;
                uint32_t b2[2] = {b0[p][o], b0[p][o + 2]};
                mma16816(acc[mt][nt], a[mt], b2);
            }
#pragma unroll
        for (int mt = 0; mt < 4; mt++) ldsm4(a[mt], (aaddr[mt] + soff) ^ 32);
#pragma unroll
        for (int mt = 0; mt < 4; mt++)
#pragma unroll
            for (int nt = 0; nt < 4; nt++) {
                int p = nt >> 1, o = nt & 1;
                uint32_t b2[2] = {b1[p][o], b1[p][o + 2]};
                mma16816(acc[mt][nt], a[mt], b2);
            }

        if (k + 5 < NK) load_stage(sl);
        cp_commit();
        s  = (s  == NSTAGE - 1) ? 0 : s + 1;
        sl = (sl == NSTAGE - 1) ? 0 : sl + 1;
    }

    // epilogue: scale by cw, atomically accumulate into out rows
#pragma unroll
    for (int mt = 0; mt < 4; mt++) {
        int r0 = wM * 64 + mt * 16 + (lane >> 2);
        int r1 = r0 + 8;
        bool v0 = (m0 + r0 < cnt), v1 = (m0 + r1 < cnt);
        float c0 = scw[r0], c1 = scw[r1];
        float* y0 = out + (size_t)stok2[r0] * H_DIM + n0;
        float* y1 = out + (size_t)stok2[r1] * H_DIM + n0;
#pragma unroll
        for (int nt = 0; nt < 4; nt++) {
            int col = wN * 32 + nt * 8 + (lane & 3) * 2;
            if (v0) {
                atomicAdd(y0 + col,     c0 * acc[mt][nt][0]);
                atomicAdd(y0 + col + 1, c0 * acc[mt][nt][1]);
            }
            if (v1) {
                atomicAdd(y1 + col,     c1 * acc[mt][nt][2]);
                atomicAdd(y1 + col + 1, c1 * acc[mt][nt][3]);
            }
        }
    }
}

// ---------------- aux ----------------------------------------------------------
__global__ void aux_kernel(float* out, int out_size) {
    if (threadIdx.x == 0 && out_size > T_TOK * H_DIM) {
        float aux = 0.f;
        for (int e = 0; e < E_NUM; e++)
            aux += ((float)d_cnt[e] / (float)T_TOK) * (d_psum[e] / (float)T_TOK);
        out[T_TOK * H_DIM] = aux * (float)E_NUM;
    }
}

// ---------------- launch -----------------------------------------------------
extern "C" void kernel_launch(void* const* d_in, const int* in_sizes, int n_in,
                              void* d_out, int out_size) {
    const float* x    = (const float*)d_in[0];
    const float* gw   = (const float*)d_in[1];
    const float* w1   = (const float*)d_in[2];
    const float* w2   = (const float*)d_in[3];
    const float* w3   = (const float*)d_in[4];
    float* out = (float*)d_out;

    cudaFuncSetAttribute(ffn1_kernel, cudaFuncAttributeMaxDynamicSharedMemorySize, F1_SMEM);
    cudaFuncSetAttribute(ffn2_kernel, cudaFuncAttributeMaxDynamicSharedMemorySize, F2_SMEM);

    cudaMemsetAsync(d_out, 0, (size_t)out_size * sizeof(float), 0);      // 1
    zero_kernel<<<1, 32>>>();                                            // 2
    gate_kernel<<<T_TOK / 8, 256>>>(x, gw);                              // 3
    cvt_w_kernel<<<(unsigned)(3ull * NW / 2048), 256>>>(w1, w2, w3);     // 4
    ffn1_kernel<<<dim3(I_DIM / 64, T_TOK / 128, E_NUM), 256, F1_SMEM>>>();  // 5
    ffn2_kernel<<<dim3(H_DIM / 128, T_TOK / 128, E_NUM), 256, F2_SMEM>>>(out); // 6
    aux_kernel<<<1, 32>>>(out, out_size);                                // 7
}

// round 17
// speedup vs baseline: 1.0278x; 1.0278x over previous
#include <cuda_runtime.h>
#include <cuda_fp16.h>
#include <math.h>
#include <stdint.h>

#define T_TOK 8192
#define H_DIM 1024
#define E_NUM 8
#define I_DIM 2048

// ---------------- device-global scratch -------------------------------------
__device__ int   d_cnt[E_NUM];
__device__ float d_psum[E_NUM];
__device__ int   d_tok[E_NUM * T_TOK];
__device__ float d_cw [E_NUM * T_TOK];

__device__ __half g_xh[(size_t)T_TOK * H_DIM];
__device__ __half g_w1h[(size_t)E_NUM * I_DIM * H_DIM];
__device__ __half g_w3h[(size_t)E_NUM * I_DIM * H_DIM];
__device__ __half g_w2h[(size_t)E_NUM * H_DIM * I_DIM];
__device__ __half g_hidh[(size_t)E_NUM * T_TOK * I_DIM];   // slot-indexed

// ---------------- PTX helpers (baseline ISA only) ----------------------------
__device__ __forceinline__ uint32_t smem_u32(const void* p) {
    uint32_t r;
    asm("{ .reg .u64 t; cvta.to.shared.u64 t, %1; cvt.u32.u64 %0, t; }"
        : "=r"(r) : "l"(p));
    return r;
}
__device__ __forceinline__ void cp16(uint32_t saddr, const void* gaddr) {
    asm volatile("cp.async.cg.shared.global [%0], [%1], 16;"
                 :: "r"(saddr), "l"(gaddr));
}
__device__ __forceinline__ void cp_commit() {
    asm volatile("cp.async.commit_group;");
}
template <int N> __device__ __forceinline__ void cp_wait() {
    asm volatile("cp.async.wait_group %0;" :: "n"(N));
}
__device__ __forceinline__ void ldsm4(uint32_t* r, uint32_t addr) {
    asm volatile("ldmatrix.sync.aligned.m8n8.x4.shared.b16 {%0,%1,%2,%3}, [%4];"
                 : "=r"(r[0]), "=r"(r[1]), "=r"(r[2]), "=r"(r[3]) : "r"(addr));
}
__device__ __forceinline__ void mma16816(float* d, const uint32_t* a,
                                         const uint32_t* b) {
    asm volatile(
        "mma.sync.aligned.m16n8k16.row.col.f32.f16.f16.f32 "
        "{%0,%1,%2,%3}, {%4,%5,%6,%7}, {%8,%9}, {%0,%1,%2,%3};"
        : "+f"(d[0]), "+f"(d[1]), "+f"(d[2]), "+f"(d[3])
        : "r"(a[0]), "r"(a[1]), "r"(a[2]), "r"(a[3]), "r"(b[0]), "r"(b[1]));
}
// vectorized global reduction: one instruction adds a float2
__device__ __forceinline__ void redg_v2(float* gaddr, float a, float b) {
    asm volatile("red.global.add.v2.f32 [%0], {%1, %2};"
                 :: "l"(gaddr), "f"(a), "f"(b) : "memory");
}
// swizzled address inside a [rows][64B] tile: conflict-free for ldmatrix+STS
__device__ __forceinline__ uint32_t tile_addr(uint32_t base, int row, int chunk) {
    return base + row * 64 + ((chunk ^ ((row >> 1) & 3)) << 4);
}
__device__ __forceinline__ uint32_t pack_h2(__half a, __half b) {
    __half2 t = __halves2half2(a, b);
    return *reinterpret_cast<uint32_t*>(&t);
}

// ---------------- small kernels ----------------------------------------------
__global__ void zero_kernel() {
    int i = threadIdx.x;
    if (i < E_NUM) { d_cnt[i] = 0; d_psum[i] = 0.f; }
}

// gate: logits/softmax/top2 + writes g_xh (fused x conversion)
__global__ void gate_kernel(const float* __restrict__ x,
                            const float* __restrict__ gw) {
    int tok  = (blockIdx.x * blockDim.x + threadIdx.x) >> 5;
    int lane = threadIdx.x & 31;
    int wib  = threadIdx.x >> 5;
    __shared__ float sprob[8][E_NUM];

    float acc[E_NUM];
#pragma unroll
    for (int e = 0; e < E_NUM; e++) acc[e] = 0.f;
    const float* xr = x + (size_t)tok * H_DIM;
    __half* xh = g_xh + (size_t)tok * H_DIM;
    for (int h = lane; h < H_DIM; h += 32) {
        float xv = xr[h];
        xh[h] = __float2half(xv);
#pragma unroll
        for (int e = 0; e < E_NUM; e++)
            acc[e] = fmaf(xv, gw[e * H_DIM + h], acc[e]);
    }
#pragma unroll
    for (int e = 0; e < E_NUM; e++)
#pragma unroll
        for (int o = 16; o > 0; o >>= 1)
            acc[e] += __shfl_xor_sync(0xffffffffu, acc[e], o);

    if (lane == 0) {
        float mx = acc[0];
#pragma unroll
        for (int e = 1; e < E_NUM; e++) mx = fmaxf(mx, acc[e]);
        float p[E_NUM], s = 0.f;
#pragma unroll
        for (int e = 0; e < E_NUM; e++) { p[e] = expf(acc[e] - mx); s += p[e]; }
        float inv = 1.f / s;
#pragma unroll
        for (int e = 0; e < E_NUM; e++) { p[e] *= inv; sprob[wib][e] = p[e]; }

        int i0 = 0; float v0 = p[0];
#pragma unroll
        for (int e = 1; e < E_NUM; e++) if (p[e] > v0) { v0 = p[e]; i0 = e; }
        int i1 = -1; float v1 = -1.f;
#pragma unroll
        for (int e = 0; e < E_NUM; e++)
            if (e != i0 && p[e] > v1) { v1 = p[e]; i1 = e; }

        float wn  = 1.f / (v0 + v1 + 1e-6f);
        int p0 = atomicAdd(&d_cnt[i0], 1);
        d_tok[i0 * T_TOK + p0] = tok;  d_cw[i0 * T_TOK + p0] = v0 * wn;
        int p1 = atomicAdd(&d_cnt[i1], 1);
        d_tok[i1 * T_TOK + p1] = tok;  d_cw[i1 * T_TOK + p1] = v1 * wn;
    }
    __syncthreads();
    if (threadIdx.x < E_NUM) {
        float s = 0.f;
#pragma unroll
        for (int w = 0; w < 8; w++) s += sprob[w][threadIdx.x];
        atomicAdd(&d_psum[threadIdx.x], s);
    }
}

// fused weight conversion (w1, w2, w3): 8 floats per thread (MLP 2)
#define NW (E_NUM * I_DIM * H_DIM)
__global__ void cvt_w_kernel(const float* __restrict__ w1,
                             const float* __restrict__ w2,
                             const float* __restrict__ w3) {
    size_t i = ((size_t)blockIdx.x * blockDim.x + threadIdx.x) * 8;
    const float* src;
    __half* dst;
    size_t off;
    if (i < NW)                  { src = w1; dst = g_w1h; off = i; }
    else if (i < 2 * (size_t)NW) { src = w2; dst = g_w2h; off = i - NW; }
    else if (i < 3 * (size_t)NW) { src = w3; dst = g_w3h; off = i - 2 * (size_t)NW; }
    else return;
    float4 v0 = *(const float4*)(src + off);
    float4 v1 = *(const float4*)(src + off + 4);
    uint4 H;
    H.x = pack_h2(__float2half(v0.x), __float2half(v0.y));
    H.y = pack_h2(__float2half(v0.z), __float2half(v0.w));
    H.z = pack_h2(__float2half(v1.x), __float2half(v1.y));
    H.w = pack_h2(__float2half(v1.z), __float2half(v1.w));
    *(uint4*)(dst + off) = H;
}

// ---------------- GEMM tile constants ----------------------------------------
// stage (16 KB): A[128][64B], B[128][64B]. 4 stages = 64 KB. 256 thr, occ 2.
#define TS_A 0
#define TS_B 8192
#define STAGE 16384
#define NSTAGE 4
#define EPI_STRIDE 68
#define F1_SMEM (NSTAGE * STAGE + 8192)  // 73728 >= epilogue 69632
#define F2_SMEM (NSTAGE * STAGE)

// ---------------- FFN1: h = silu(x w1^T) * (x w3^T) --------------------------
// block tile: M=128 routed rows, N=64 intermediate cols for both w1 & w3.
// B smem rows 0-63 = w1h[n0..], 64-127 = w3h[n0..]. 8 warps (wM 0-1)x(wN 0-3).
__global__ void __launch_bounds__(256, 2)
ffn1_kernel() {
    extern __shared__ char smem[];
    __shared__ int stok[128];
    const int e   = blockIdx.z;
    const int cnt = d_cnt[e];
    const int m0  = blockIdx.y * 128;
    if (m0 >= cnt) return;
    const int n0  = blockIdx.x * 64;

    const uint32_t sb = smem_u32(smem);
    const int tid = threadIdx.x, lane = tid & 31, wid = tid >> 5;
    const int wM = wid >> 2, wN = wid & 3;

    if (tid < 128) stok[tid] = (m0 + tid < cnt) ? d_tok[e * T_TOK + m0 + tid] : 0;
    __syncthreads();

    // ---- precomputed loader state: pure pointer-increment per stage ----
    const __half* gsrc[4];
    uint32_t sdst[4];
#pragma unroll
    for (int t = 0; t < 4; t++) {
        int i = tid + t * 256;
        int region = i >> 9;          // 0 A, 1 B
        int idx = i & 511;
        int row = idx >> 2, c = idx & 3;
        sdst[t] = tile_addr(sb + region * 8192, row, c);
        if (region == 0) {
            gsrc[t] = g_xh + (size_t)stok[row] * H_DIM + c * 8;
        } else {
            const __half* s_ = (row < 64) ? g_w1h : g_w3h;
            int r = row & 63;
            gsrc[t] = s_ + ((size_t)e * I_DIM + n0 + r) * H_DIM + c * 8;
        }
    }
    auto load_stage = [&](int s) {
#pragma unroll
        for (int t = 0; t < 4; t++) {
            cp16(sdst[t] + s * STAGE, gsrc[t]);
            gsrc[t] += 32;
        }
    };

    // ---- ldmatrix addresses for ks=0; ks=1 = addr ^ 32 (swizzle identity) ----
    uint32_t aaddr[4], baddr[2];
    {
        const int cb = (lane >> 4);
#pragma unroll
        for (int mt = 0; mt < 4; mt++)
            aaddr[mt] = tile_addr(sb + TS_A, wM * 64 + mt * 16 + (lane & 15), cb);
#pragma unroll
        for (int p = 0; p < 2; p++)
            baddr[p] = tile_addr(sb + TS_B, wN * 32 + p * 16 + (lane & 15), cb);
    }

    float acc[4][4][4];
#pragma unroll
    for (int mt = 0; mt < 4; mt++)
#pragma unroll
        for (int nt = 0; nt < 4; nt++)
#pragma unroll
            for (int q = 0; q < 4; q++) acc[mt][nt][q] = 0.f;

    const int NK = H_DIM / 32;
    load_stage(0); cp_commit();
    load_stage(1); cp_commit();
    load_stage(2); cp_commit();

    for (int k = 0; k < NK; k++) {
        cp_wait<2>();
        __syncthreads();
        const uint32_t soff = (k & 3) * STAGE;

        uint32_t a[4][4], b0[2][4], b1[2][4];
#pragma unroll
        for (int mt = 0; mt < 4; mt++) ldsm4(a[mt], aaddr[mt] + soff);
#pragma unroll
        for (int p = 0; p < 2; p++)    ldsm4(b0[p], baddr[p] + soff);
#pragma unroll
        for (int p = 0; p < 2; p++)    ldsm4(b1[p], (baddr[p] + soff) ^ 32);
        // ks = 0
#pragma unroll
        for (int mt = 0; mt < 4; mt++)
#pragma unroll
            for (int nt = 0; nt < 4; nt++) {
                int p = nt >> 1, o = nt & 1;
                uint32_t b2[2] = {b0[p][o], b0[p][o + 2]};
                mma16816(acc[mt][nt], a[mt], b2);
            }
        // ks = 1 (reuse A register set)
#pragma unroll
        for (int mt = 0; mt < 4; mt++) ldsm4(a[mt], (aaddr[mt] + soff) ^ 32);
#pragma unroll
        for (int mt = 0; mt < 4; mt++)
#pragma unroll
            for (int nt = 0; nt < 4; nt++) {
                int p = nt >> 1, o = nt & 1;
                uint32_t b2[2] = {b1[p][o], b1[p][o + 2]};
                mma16816(acc[mt][nt], a[mt], b2);
            }

        if (k + 3 < NK) load_stage((k + 3) & 3);
        cp_commit();
    }
    __syncthreads();   // before epilogue aliases stage smem

    // epilogue: stash g/u in smem, combine, convert to fp16
    float* Sg = (float*)smem;
    float* Su = Sg + 128 * EPI_STRIDE;
    float* Sacc = (wN < 2) ? Sg : Su;
    const int ncb = (wN & 1) * 32;
#pragma unroll
    for (int mt = 0; mt < 4; mt++) {
        int row = wM * 64 + mt * 16 + (lane >> 2);
#pragma unroll
        for (int nt = 0; nt < 4; nt++) {
            int col = ncb + nt * 8 + (lane & 3) * 2;
            Sacc[row * EPI_STRIDE + col]     = acc[mt][nt][0];
            Sacc[row * EPI_STRIDE + col + 1] = acc[mt][nt][1];
            Sacc[(row + 8) * EPI_STRIDE + col]     = acc[mt][nt][2];
            Sacc[(row + 8) * EPI_STRIDE + col + 1] = acc[mt][nt][3];
        }
    }
    __syncthreads();

    const size_t slotbase = (size_t)e * T_TOK + m0;
    for (int idx = tid; idx < 128 * 32; idx += 256) {
        int m = idx >> 5;
        if (m0 + m >= cnt) continue;
        int c = (idx & 31) * 2;
        float g0 = Sg[m * EPI_STRIDE + c], g1 = Sg[m * EPI_STRIDE + c + 1];
        float u0 = Su[m * EPI_STRIDE + c], u1 = Su[m * EPI_STRIDE + c + 1];
        float h0 = (g0 / (1.f + __expf(-g0))) * u0;
        float h1 = (g1 / (1.f + __expf(-g1))) * u1;
        *(uint32_t*)(g_hidh + (slotbase + m) * I_DIM + n0 + c) =
            pack_h2(__float2half(h0), __float2half(h1));
    }
}

// ---------------- FFN2: out[tok] += cw * (hidden w2^T) -----------------------
// block tile M=128, N=128 (H cols). 8 warps (wM 0-1)x(wN 0-3), 64x32 each.
// Writes straight to out with vectorized red.global.add.v2.f32 (out pre-zeroed).
__global__ void __launch_bounds__(256, 2)
ffn2_kernel(float* __restrict__ out) {
    extern __shared__ char smem[];
    __shared__ float scw[128];
    __shared__ int   stok2[128];
    const int e   = blockIdx.z;
    const int cnt = d_cnt[e];
    const int m0  = blockIdx.y * 128;
    if (m0 >= cnt) return;
    const int n0  = blockIdx.x * 128;
    const size_t slotbase = (size_t)e * T_TOK + m0;

    const uint32_t sb = smem_u32(smem);
    const int tid = threadIdx.x, lane = tid & 31, wid = tid >> 5;
    const int wM = wid >> 2, wN = wid & 3;

    if (tid < 128) {
        bool v = (m0 + tid < cnt);
        scw[tid]   = v ? d_cw[e * T_TOK + m0 + tid] : 0.f;
        stok2[tid] = v ? d_tok[e * T_TOK + m0 + tid] : 0;
    }
    __syncthreads();

    const __half* gsrc[4];
    uint32_t sdst[4];
#pragma unroll
    for (int t = 0; t < 4; t++) {
        int i = tid + t * 256;
        int region = i >> 9;
        int idx = i & 511;
        int row = idx >> 2, c = idx & 3;
        sdst[t] = tile_addr(sb + region * 8192, row, c);
        if (region == 0)
            gsrc[t] = g_hidh + (slotbase + row) * I_DIM + c * 8;
        else
            gsrc[t] = g_w2h + ((size_t)e * H_DIM + n0 + row) * I_DIM + c * 8;
    }
    auto load_stage = [&](int s) {
#pragma unroll
        for (int t = 0; t < 4; t++) {
            cp16(sdst[t] + s * STAGE, gsrc[t]);
            gsrc[t] += 32;
        }
    };

    uint32_t aaddr[4], baddr[2];
    {
        const int cb = (lane >> 4);
#pragma unroll
        for (int mt = 0; mt < 4; mt++)
            aaddr[mt] = tile_addr(sb + TS_A, wM * 64 + mt * 16 + (lane & 15), cb);
#pragma unroll
        for (int p = 0; p < 2; p++)
            baddr[p] = tile_addr(sb + TS_B, wN * 32 + p * 16 + (lane & 15), cb);
    }

    float acc[4][4][4];
#pragma unroll
    for (int mt = 0; mt < 4; mt++)
#pragma unroll
        for (int nt = 0; nt < 4; nt++)
#pragma unroll
            for (int q = 0; q < 4; q++) acc[mt][nt][q] = 0.f;

    const int NK = I_DIM / 32;
    load_stage(0); cp_commit();
    load_stage(1); cp_commit();
    load_stage(2); cp_commit();

    for (int k = 0; k < NK; k++) {
        cp_wait<2>();
        __syncthreads();
        const uint32_t soff = (k & 3) * STAGE;

        uint32_t a[4][4], b0[2][4], b1[2][4];
#pragma unroll
        for (int mt = 0; mt < 4; mt++) ldsm4(a[mt], aaddr[mt] + soff);
#pragma unroll
        for (int p = 0; p < 2; p++)    ldsm4(b0[p], baddr[p] + soff);
#pragma unroll
        for (int p = 0; p < 2; p++)    ldsm4(b1[p], (baddr[p] + soff) ^ 32);
#pragma unroll
        for (int mt = 0; mt < 4; mt++)
#pragma unroll
            for (int nt = 0; nt < 4; nt++) {
                int p = nt >> 1, o = nt & 1;
                uint32_t b2[2] = {b0[p][o], b0[p][o + 2]};
                mma16816(acc[mt][nt], a[mt], b2);
            }
#pragma unroll
        for (int mt = 0; mt < 4; mt++) ldsm4(a[mt], (aaddr[mt] + soff) ^ 32);
#pragma unroll
        for (int mt = 0; mt < 4; mt++)
#pragma unroll
            for (int nt = 0; nt < 4; nt++) {
                int p = nt >> 1, o = nt & 1;
                uint32_t b2[2] = {b1[p][o], b1[p][o + 2]};
                mma16816(acc[mt][nt], a[mt], b2);
            }

        if (k + 3 < NK) load_stage((k + 3) & 3);
        cp_commit();
    }

    // epilogue: scale by cw, vector-reduce into out rows
#pragma unroll
    for (int mt = 0; mt < 4; mt++) {
        int r0 = wM * 64 + mt * 16 + (lane >> 2);
        int r1 = r0 + 8;
        bool v0 = (m0 + r0 < cnt), v1 = (m0 + r1 < cnt);
        float c0 = scw[r0], c1 = scw[r1];
        float* y0 = out + (size_t)stok2[r0] * H_DIM + n0;
        float* y1 = out + (size_t)stok2[r1] * H_DIM + n0;
#pragma unroll
        for (int nt = 0; nt < 4; nt++) {
            int col = wN * 32 + nt * 8 + (lane & 3) * 2;
            if (v0) redg_v2(y0 + col, c0 * acc[mt][nt][0], c0 * acc[mt][nt][1]);
            if (v1) redg_v2(y1 + col, c1 * acc[mt][nt][2], c1 * acc[mt][nt][3]);
        }
    }
}

// ---------------- aux ----------------------------------------------------------
__global__ void aux_kernel(float* out, int out_size) {
    if (threadIdx.x == 0 && out_size > T_TOK * H_DIM) {
        float aux = 0.f;
        for (int e = 0; e < E_NUM; e++)
            aux += ((float)d_cnt[e] / (float)T_TOK) * (d_psum[e] / (float)T_TOK);
        out[T_TOK * H_DIM] = aux * (float)E_NUM;
    }
}

// ---------------- launch -----------------------------------------------------
extern "C" void kernel_launch(void* const* d_in, const int* in_sizes, int n_in,
                              void* d_out, int out_size) {
    const float* x    = (const float*)d_in[0];
    const float* gw   = (const float*)d_in[1];
    const float* w1   = (const float*)d_in[2];
    const float* w2   = (const float*)d_in[3];
    const float* w3   = (const float*)d_in[4];
    float* out = (float*)d_out;

    cudaFuncSetAttribute(ffn1_kernel, cudaFuncAttributeMaxDynamicSharedMemorySize, F1_SMEM);
    cudaFuncSetAttribute(ffn2_kernel, cudaFuncAttributeMaxDynamicSharedMemorySize, F2_SMEM);

    cudaMemsetAsync(d_out, 0, (size_t)out_size * sizeof(float), 0);      // 1
    zero_kernel<<<1, 32>>>();                                            // 2
    gate_kernel<<<T_TOK / 8, 256>>>(x, gw);                              // 3
    cvt_w_kernel<<<(unsigned)(3ull * NW / 2048), 256>>>(w1, w2, w3);     // 4
    ffn1_kernel<<<dim3(I_DIM / 64, T_TOK / 128, E_NUM), 256, F1_SMEM>>>();  // 5
    ffn2_kernel<<<dim3(H_DIM / 128, T_TOK / 128, E_NUM), 256, F2_SMEM>>>(out); // 6
    aux_kernel<<<1, 32>>>(out, out_size);                                // 7
}